// round 16
// baseline (speedup 1.0000x reference)
#include <cuda_runtime.h>
#include <cuda_bf16.h>
#include <cstdint>

#define TB 4
#define TS 4096
#define TH 1024
#define TE 8
#define TD 256
#define TT (TB*TS)   // 16384 tokens

// ================= device scratch (static; referenced from device code only) =====
__device__ __align__(16) int   g_expert_of[TT];
__device__ __align__(16) int   g_count[TE];
__device__ __align__(16) int   g_offset[TE+1];
__device__ __align__(16) int   g_cursor[TE];
__device__ __align__(16) int   g_token_list[TT];
__device__ __align__(16) float g_inter[(size_t)TT*TD];   // permuted-order rows, fp32

// ================= helpers =================
__device__ __forceinline__ uint32_t smem_to_u32(const void* p) {
    uint32_t a;
    asm("{ .reg .u64 t; cvta.to.shared.u64 t, %1; cvt.u32.u64 %0, t; }" : "=r"(a) : "l"(p));
    return a;
}
__device__ __forceinline__ void ldm_x4(uint32_t& r0, uint32_t& r1, uint32_t& r2, uint32_t& r3, uint32_t addr) {
    asm volatile("ldmatrix.sync.aligned.m8n8.x4.shared.b16 {%0,%1,%2,%3}, [%4];"
                 : "=r"(r0), "=r"(r1), "=r"(r2), "=r"(r3) : "r"(addr));
}
__device__ __forceinline__ void mma_bf16(float* c, const uint32_t* a, const uint32_t* b) {
    asm volatile("mma.sync.aligned.m16n8k16.row.col.f32.bf16.bf16.f32 "
                 "{%0,%1,%2,%3}, {%4,%5,%6,%7}, {%8,%9}, {%0,%1,%2,%3};"
                 : "+f"(c[0]), "+f"(c[1]), "+f"(c[2]), "+f"(c[3])
                 : "r"(a[0]), "r"(a[1]), "r"(a[2]), "r"(a[3]), "r"(b[0]), "r"(b[1]));
}
__device__ __forceinline__ void split_bf16(float v, __nv_bfloat16& h, __nv_bfloat16& l) {
    h = __float2bfloat16_rn(v);
    l = __float2bfloat16_rn(v - __bfloat162float(h));
}
#define RPAD 40   // bf16 elems per SMEM row (80B) -> conflict-free ldmatrix rows

// ================= kernel 0: zero =================
__global__ void k_zero() {
    int i = threadIdx.x;
    if (i < TE) { g_count[i] = 0; g_cursor[i] = 0; }
}

// ================= kernel 1: router =================
__global__ void k_router(const float* __restrict__ x, const float* __restrict__ gw) {
    __shared__ float sgw[TE*TH];
    for (int i = threadIdx.x; i < TE*TH; i += blockDim.x) sgw[i] = gw[i];
    __syncthreads();
    int warp = threadIdx.x >> 5, lane = threadIdx.x & 31;
    int t = blockIdx.x * 8 + warp;
    if (t >= TT) return;
    const float* xr = x + (size_t)t * TH;
    float acc[TE];
#pragma unroll
    for (int e = 0; e < TE; e++) acc[e] = 0.f;
#pragma unroll 4
    for (int i = 0; i < TH/32; i++) {
        float xv = xr[i*32 + lane];
#pragma unroll
        for (int e = 0; e < TE; e++) acc[e] += xv * sgw[e*TH + i*32 + lane];
    }
#pragma unroll
    for (int off = 16; off; off >>= 1)
#pragma unroll
        for (int e = 0; e < TE; e++) acc[e] += __shfl_xor_sync(0xFFFFFFFFu, acc[e], off);
    if (lane == 0) {
        int best = 0; float bv = acc[0];
#pragma unroll
        for (int e = 1; e < TE; e++) if (acc[e] > bv) { bv = acc[e]; best = e; }
        g_expert_of[t] = best;
        atomicAdd(&g_count[best], 1);
    }
}

// ================= kernel 2: scan =================
__global__ void k_scan() {
    if (threadIdx.x == 0) {
        int s = 0;
        for (int e = 0; e < TE; e++) { g_offset[e] = s; s += g_count[e]; }
        g_offset[TE] = s;
    }
}

// ================= kernel 3: scatter =================
__global__ void k_scatter() {
    int t = blockIdx.x * blockDim.x + threadIdx.x;
    if (t < TT) {
        int e = g_expert_of[t];
        int p = g_offset[e] + atomicAdd(&g_cursor[e], 1);
        g_token_list[p] = t;
    }
}

// ================= kernel 4: up+gate HMMA GEMM, double-buffered =========
#define SA_HI 0
#define SA_LO (128*RPAD)
#define SBGH  (2*128*RPAD)
#define SBGL  (2*128*RPAD + 64*RPAD)
#define SBUH  (2*128*RPAD + 2*64*RPAD)
#define SBUL  (2*128*RPAD + 3*64*RPAD)
#define G1_STAGE_ELEMS (2*128*RPAD + 4*64*RPAD)          // 20480
#define G1_SMEM_BYTES  (2*G1_STAGE_ELEMS*2)              // 81920
__global__ __launch_bounds__(256, 1) void k_upgate_mma(const float* __restrict__ x,
                                                       const float* __restrict__ wg,
                                                       const float* __restrict__ wu) {
    extern __shared__ __align__(16) __nv_bfloat16 sm[];
    __shared__ int rowsS[128];
    const int tid = threadIdx.x, wid = tid >> 5, lane = tid & 31;
    const int e = blockIdx.z;
    const int off = g_offset[e];
    const int cnt = g_offset[e+1] - off;
    const int m0 = blockIdx.x * 128;
    if (m0 >= cnt) return;
    const int n0 = blockIdx.y * 64;
    const int valid = (cnt - m0 < 128) ? (cnt - m0) : 128;

    if (tid < 128) {
        int m = m0 + tid;
        rowsS[tid] = (m < cnt) ? g_token_list[off + m] : -1;
    }
    __syncthreads();

    const float* wge = wg + (size_t)e * TH * TD;
    const float* wue = wu + (size_t)e * TH * TD;

    // A loader: thread -> (row, half): 16 consecutive k each
    const int arow = tid >> 1, ahalf = tid & 1;
    int tokA = rowsS[arow];
    if (tokA < 0) tokA = rowsS[0];
    const float* asrc = x + (size_t)tokA * TH + ahalf * 16;
    // B loader: thread -> (n, 8 k values)
    const int bn = tid & 63, bk8 = (tid >> 6) * 8;

    float cG[2][4][4], cU[2][4][4];
#pragma unroll
    for (int a = 0; a < 2; a++)
#pragma unroll
        for (int b = 0; b < 4; b++)
#pragma unroll
            for (int c = 0; c < 4; c++) { cG[a][b][c] = 0.f; cU[a][b][c] = 0.f; }

    const int wm = wid & 3, wn = wid >> 2;
    const uint32_t sb32 = smem_to_u32(sm);
    const int a_lr = ((lane >> 3) & 1) * 8 + (lane & 7);
    const int a_lk = (lane >> 4) * 8;
    const int b_lr = ((lane >> 4) & 1) * 8 + (lane & 7);
    const int b_lk = ((lane >> 3) & 1) * 8;
    const int qrow = lane >> 2, qcol = (lane & 3) * 2;

    float4 pa[4];
    float  pg[8], pu[8];
#define G1_LOAD_REGS(c) do {                                              \
        int _k0 = (c) * 32;                                               \
        _Pragma("unroll")                                                 \
        for (int j = 0; j < 4; j++) pa[j] = *(const float4*)(asrc + _k0 + j*4); \
        _Pragma("unroll")                                                 \
        for (int j = 0; j < 8; j++) pg[j] = wge[(size_t)(_k0 + bk8 + j) * TD + n0 + bn]; \
        _Pragma("unroll")                                                 \
        for (int j = 0; j < 8; j++) pu[j] = wue[(size_t)(_k0 + bk8 + j) * TD + n0 + bn]; \
    } while (0)

#define G1_STORE(bufbase) do {                                            \
        __nv_bfloat16* _bp = (bufbase);                                   \
        __align__(16) __nv_bfloat16 hb[16], lb[16];                       \
        _Pragma("unroll")                                                 \
        for (int j = 0; j < 4; j++) {                                     \
            split_bf16(pa[j].x, hb[j*4+0], lb[j*4+0]);                    \
            split_bf16(pa[j].y, hb[j*4+1], lb[j*4+1]);                    \
            split_bf16(pa[j].z, hb[j*4+2], lb[j*4+2]);                    \
            split_bf16(pa[j].w, hb[j*4+3], lb[j*4+3]);                    \
        }                                                                 \
        uint32_t ao = arow*RPAD + ahalf*16;                               \
        *(uint4*)(_bp + SA_HI + ao)     = ((uint4*)hb)[0];                \
        *(uint4*)(_bp + SA_HI + ao + 8) = ((uint4*)hb)[1];                \
        *(uint4*)(_bp + SA_LO + ao)     = ((uint4*)lb)[0];                \
        *(uint4*)(_bp + SA_LO + ao + 8) = ((uint4*)lb)[1];                \
        _Pragma("unroll")                                                 \
        for (int j = 0; j < 8; j++) split_bf16(pg[j], hb[j], lb[j]);      \
        *(uint4*)(_bp + SBGH + bn*RPAD + bk8) = *(uint4*)hb;              \
        *(uint4*)(_bp + SBGL + bn*RPAD + bk8) = *(uint4*)lb;              \
        _Pragma("unroll")                                                 \
        for (int j = 0; j < 8; j++) split_bf16(pu[j], hb[j], lb[j]);      \
        *(uint4*)(_bp + SBUH + bn*RPAD + bk8) = *(uint4*)hb;              \
        *(uint4*)(_bp + SBUL + bn*RPAD + bk8) = *(uint4*)lb;              \
    } while (0)

    const int NC = TH / 32;   // 32
    G1_LOAD_REGS(0);
    G1_STORE(sm);
    __syncthreads();
    for (int c = 0; c < NC; c++) {
        if (c + 1 < NC) G1_LOAD_REGS(c + 1);
        const uint32_t sbc = sb32 + (uint32_t)(c & 1) * (G1_STAGE_ELEMS * 2);
        // ---- compute chunk c ----
#pragma unroll
        for (int ks = 0; ks < 2; ks++) {
            uint32_t bGh[8], bGl[8], bUh[8], bUl[8];
#pragma unroll
            for (int p = 0; p < 2; p++) {
                uint32_t ro = (uint32_t)((wn*32 + p*16 + b_lr)*RPAD + ks*16 + b_lk) * 2;
                ldm_x4(bGh[p*4+0], bGh[p*4+1], bGh[p*4+2], bGh[p*4+3], sbc + SBGH*2 + ro);
                ldm_x4(bGl[p*4+0], bGl[p*4+1], bGl[p*4+2], bGl[p*4+3], sbc + SBGL*2 + ro);
                ldm_x4(bUh[p*4+0], bUh[p*4+1], bUh[p*4+2], bUh[p*4+3], sbc + SBUH*2 + ro);
                ldm_x4(bUl[p*4+0], bUl[p*4+1], bUl[p*4+2], bUl[p*4+3], sbc + SBUL*2 + ro);
            }
#pragma unroll
            for (int mt = 0; mt < 2; mt++) {
                uint32_t ao = (uint32_t)((wm*32 + mt*16 + a_lr)*RPAD + ks*16 + a_lk) * 2;
                uint32_t aH[4], aL[4];
                ldm_x4(aH[0], aH[1], aH[2], aH[3], sbc + SA_HI*2 + ao);
                ldm_x4(aL[0], aL[1], aL[2], aL[3], sbc + SA_LO*2 + ao);
#pragma unroll
                for (int nt = 0; nt < 4; nt++) {
                    mma_bf16(cG[mt][nt], aH, &bGh[nt*2]);
                    mma_bf16(cG[mt][nt], aH, &bGl[nt*2]);
                    mma_bf16(cG[mt][nt], aL, &bGh[nt*2]);
                    mma_bf16(cU[mt][nt], aH, &bUh[nt*2]);
                    mma_bf16(cU[mt][nt], aH, &bUl[nt*2]);
                    mma_bf16(cU[mt][nt], aL, &bUh[nt*2]);
                }
            }
        }
        // ---- store chunk c+1 into the other buffer (overlaps nothing it reads) ----
        if (c + 1 < NC) G1_STORE(sm + ((c + 1) & 1) * G1_STAGE_ELEMS);
        __syncthreads();
    }

    // epilogue: inter = relu(g)^2 * u, fp32 store to permuted rows
#pragma unroll
    for (int mt = 0; mt < 2; mt++)
#pragma unroll
        for (int h = 0; h < 2; h++) {
            int rr = wm*32 + mt*16 + qrow + h*8;
            if (rr < valid) {
                float* rowp = g_inter + (size_t)(off + m0 + rr) * TD + n0;
#pragma unroll
                for (int nt = 0; nt < 4; nt++) {
                    float g0 = fmaxf(cG[mt][nt][h*2+0], 0.f);
                    float g1 = fmaxf(cG[mt][nt][h*2+1], 0.f);
                    float2 v = make_float2(g0*g0*cU[mt][nt][h*2+0],
                                           g1*g1*cU[mt][nt][h*2+1]);
                    *(float2*)(rowp + wn*32 + nt*8 + qcol) = v;
                }
            }
        }
}

// ================= kernel 5: down-proj HMMA GEMM, double-buffered =================
#define D_SA_HI 0
#define D_SA_LO (128*RPAD)
#define D_SBH   (2*128*RPAD)
#define D_SBL   (2*128*RPAD + 64*RPAD)
#define G2_STAGE_ELEMS (2*128*RPAD + 2*64*RPAD)          // 15360
#define G2_SMEM_BYTES  (2*G2_STAGE_ELEMS*2)              // 61440
__global__ __launch_bounds__(256, 1) void k_down_mma(const float* __restrict__ wd,
                                                     float* __restrict__ out) {
    extern __shared__ __align__(16) __nv_bfloat16 sm[];
    __shared__ int rowsS[128];
    const int tid = threadIdx.x, wid = tid >> 5, lane = tid & 31;
    const int e = blockIdx.z;
    const int off = g_offset[e];
    const int cnt = g_offset[e+1] - off;
    const int m0 = blockIdx.x * 128;
    if (m0 >= cnt) return;
    const int n0 = blockIdx.y * 64;
    const int valid = (cnt - m0 < 128) ? (cnt - m0) : 128;

    if (tid < 128) {
        int m = m0 + tid;
        rowsS[tid] = (m < cnt) ? g_token_list[off + m] : -1;
    }
    __syncthreads();

    const float* wde = wd + (size_t)e * TD * TH;

    const int arow = tid >> 1, ahalf = tid & 1;
    const int arowc = (arow < valid) ? arow : (valid - 1);
    const float* asrc = g_inter + (size_t)(off + m0 + arowc) * TD + ahalf * 16;
    const int bn = tid & 63, bk8 = (tid >> 6) * 8;

    float cc[2][4][4];
#pragma unroll
    for (int a = 0; a < 2; a++)
#pragma unroll
        for (int b = 0; b < 4; b++)
#pragma unroll
            for (int c = 0; c < 4; c++) cc[a][b][c] = 0.f;

    const int wm = wid & 3, wn = wid >> 2;
    const uint32_t sb32 = smem_to_u32(sm);
    const int a_lr = ((lane >> 3) & 1) * 8 + (lane & 7);
    const int a_lk = (lane >> 4) * 8;
    const int b_lr = ((lane >> 4) & 1) * 8 + (lane & 7);
    const int b_lk = ((lane >> 3) & 1) * 8;
    const int qrow = lane >> 2, qcol = (lane & 3) * 2;

    float4 pa[4];
    float  pb[8];
#define G2_LOAD_REGS(c) do {                                              \
        int _k0 = (c) * 32;                                               \
        _Pragma("unroll")                                                 \
        for (int j = 0; j < 4; j++) pa[j] = *(const float4*)(asrc + _k0 + j*4); \
        _Pragma("unroll")                                                 \
        for (int j = 0; j < 8; j++) pb[j] = wde[(size_t)(_k0 + bk8 + j) * TH + n0 + bn]; \
    } while (0)

#define G2_STORE(bufbase) do {                                            \
        __nv_bfloat16* _bp = (bufbase);                                   \
        __align__(16) __nv_bfloat16 hb[16], lb[16];                       \
        _Pragma("unroll")                                                 \
        for (int j = 0; j < 4; j++) {                                     \
            split_bf16(pa[j].x, hb[j*4+0], lb[j*4+0]);                    \
            split_bf16(pa[j].y, hb[j*4+1], lb[j*4+1]);                    \
            split_bf16(pa[j].z, hb[j*4+2], lb[j*4+2]);                    \
            split_bf16(pa[j].w, hb[j*4+3], lb[j*4+3]);                    \
        }                                                                 \
        uint32_t ao = arow*RPAD + ahalf*16;                               \
        *(uint4*)(_bp + D_SA_HI + ao)     = ((uint4*)hb)[0];              \
        *(uint4*)(_bp + D_SA_HI + ao + 8) = ((uint4*)hb)[1];              \
        *(uint4*)(_bp + D_SA_LO + ao)     = ((uint4*)lb)[0];              \
        *(uint4*)(_bp + D_SA_LO + ao + 8) = ((uint4*)lb)[1];              \
        _Pragma("unroll")                                                 \
        for (int j = 0; j < 8; j++) split_bf16(pb[j], hb[j], lb[j]);      \
        *(uint4*)(_bp + D_SBH + bn*RPAD + bk8) = *(uint4*)hb;             \
        *(uint4*)(_bp + D_SBL + bn*RPAD + bk8) = *(uint4*)lb;             \
    } while (0)

    const int NC = TD / 32;   // 8
    G2_LOAD_REGS(0);
    G2_STORE(sm);
    __syncthreads();
    for (int c = 0; c < NC; c++) {
        if (c + 1 < NC) G2_LOAD_REGS(c + 1);
        const uint32_t sbc = sb32 + (uint32_t)(c & 1) * (G2_STAGE_ELEMS * 2);
#pragma unroll
        for (int ks = 0; ks < 2; ks++) {
            uint32_t bH[8], bL[8];
#pragma unroll
            for (int p = 0; p < 2; p++) {
                uint32_t ro = (uint32_t)((wn*32 + p*16 + b_lr)*RPAD + ks*16 + b_lk) * 2;
                ldm_x4(bH[p*4+0], bH[p*4+1], bH[p*4+2], bH[p*4+3], sbc + D_SBH*2 + ro);
                ldm_x4(bL[p*4+0], bL[p*4+1], bL[p*4+2], bL[p*4+3], sbc + D_SBL*2 + ro);
            }
#pragma unroll
            for (int mt = 0; mt < 2; mt++) {
                uint32_t ao = (uint32_t)((wm*32 + mt*16 + a_lr)*RPAD + ks*16 + a_lk) * 2;
                uint32_t aH[4], aL[4];
                ldm_x4(aH[0], aH[1], aH[2], aH[3], sbc + D_SA_HI*2 + ao);
                ldm_x4(aL[0], aL[1], aL[2], aL[3], sbc + D_SA_LO*2 + ao);
#pragma unroll
                for (int nt = 0; nt < 4; nt++) {
                    mma_bf16(cc[mt][nt], aH, &bH[nt*2]);
                    mma_bf16(cc[mt][nt], aH, &bL[nt*2]);
                    mma_bf16(cc[mt][nt], aL, &bH[nt*2]);
                }
            }
        }
        if (c + 1 < NC) G2_STORE(sm + ((c + 1) & 1) * G2_STAGE_ELEMS);
        __syncthreads();
    }

    // epilogue: scatter-store fp32 pairs to out[token]
#pragma unroll
    for (int mt = 0; mt < 2; mt++)
#pragma unroll
        for (int h = 0; h < 2; h++) {
            int rr = wm*32 + mt*16 + qrow + h*8;
            int tok = rowsS[rr];
            if (tok >= 0) {
                float* rowp = out + (size_t)tok * TH + n0;
#pragma unroll
                for (int nt = 0; nt < 4; nt++) {
                    float2 v = make_float2(cc[mt][nt][h*2+0], cc[mt][nt][h*2+1]);
                    *(float2*)(rowp + wn*32 + nt*8 + qcol) = v;
                }
            }
        }
}

// ================= launch =================
extern "C" void kernel_launch(void* const* d_in, const int* in_sizes, int n_in,
                              void* d_out, int out_size) {
    const float* x  = (const float*)d_in[0];   // [B,S,H]
    const float* gw = (const float*)d_in[1];   // [E,H]
    const float* wg = (const float*)d_in[2];   // [E,H,D]
    const float* wu = (const float*)d_in[3];   // [E,H,D]
    const float* wd = (const float*)d_in[4];   // [E,D,H]
    float* out = (float*)d_out;

    cudaFuncSetAttribute(k_upgate_mma, cudaFuncAttributeMaxDynamicSharedMemorySize, G1_SMEM_BYTES);
    cudaFuncSetAttribute(k_down_mma,   cudaFuncAttributeMaxDynamicSharedMemorySize, G2_SMEM_BYTES);

    k_zero<<<1, 32>>>();
    k_router<<<TT/8, 256>>>(x, gw);
    k_scan<<<1, 32>>>();
    k_scatter<<<TT/256, 256>>>();
    {
        dim3 grid(TT/128, TD/64, TE);   // (128, 4, 8); idle tiles exit on count check
        k_upgate_mma<<<grid, 256, G1_SMEM_BYTES>>>(x, wg, wu);
    }
    {
        dim3 grid(TT/128, TH/64, TE);   // (128, 16, 8)
        k_down_mma<<<grid, 256, G2_SMEM_BYTES>>>(wd, out);
    }
}

// round 17
// speedup vs baseline: 1.3057x; 1.3057x over previous
#include <cuda_runtime.h>
#include <cuda_fp16.h>
#include <cstdint>

#define TB 4
#define TS 4096
#define TH 1024
#define TE 8
#define TD 256
#define TT (TB*TS)   // 16384 tokens

// ================= device scratch (static; referenced from device code only) =====
__device__ __align__(16) int   g_expert_of[TT];
__device__ __align__(16) int   g_count[TE];
__device__ __align__(16) int   g_offset[TE+1];
__device__ __align__(16) int   g_cursor[TE];
__device__ __align__(16) int   g_token_list[TT];
__device__ __align__(16) float g_inter[(size_t)TT*TD];   // permuted-order rows, fp32

// ================= helpers =================
__device__ __forceinline__ uint32_t smem_to_u32(const void* p) {
    uint32_t a;
    asm("{ .reg .u64 t; cvta.to.shared.u64 t, %1; cvt.u32.u64 %0, t; }" : "=r"(a) : "l"(p));
    return a;
}
__device__ __forceinline__ void ldm_x4(uint32_t& r0, uint32_t& r1, uint32_t& r2, uint32_t& r3, uint32_t addr) {
    asm volatile("ldmatrix.sync.aligned.m8n8.x4.shared.b16 {%0,%1,%2,%3}, [%4];"
                 : "=r"(r0), "=r"(r1), "=r"(r2), "=r"(r3) : "r"(addr));
}
__device__ __forceinline__ void mma_f16(float* c, const uint32_t* a, const uint32_t* b) {
    asm volatile("mma.sync.aligned.m16n8k16.row.col.f32.f16.f16.f32 "
                 "{%0,%1,%2,%3}, {%4,%5,%6,%7}, {%8,%9}, {%0,%1,%2,%3};"
                 : "+f"(c[0]), "+f"(c[1]), "+f"(c[2]), "+f"(c[3])
                 : "r"(a[0]), "r"(a[1]), "r"(a[2]), "r"(a[3]), "r"(b[0]), "r"(b[1]));
}
__device__ __forceinline__ void split_f16(float v, __half& h, __half& l) {
    h = __float2half_rn(v);
    l = __float2half_rn(v - __half2float(h));
}
#define RPAD 40   // f16 elems per SMEM row (80B) -> conflict-free ldmatrix rows

// ================= kernel 0: zero =================
__global__ void k_zero() {
    int i = threadIdx.x;
    if (i < TE) { g_count[i] = 0; g_cursor[i] = 0; }
}

// ================= kernel 1: router =================
__global__ void k_router(const float* __restrict__ x, const float* __restrict__ gw) {
    __shared__ float sgw[TE*TH];
    for (int i = threadIdx.x; i < TE*TH; i += blockDim.x) sgw[i] = gw[i];
    __syncthreads();
    int warp = threadIdx.x >> 5, lane = threadIdx.x & 31;
    int t = blockIdx.x * 8 + warp;
    if (t >= TT) return;
    const float* xr = x + (size_t)t * TH;
    float acc[TE];
#pragma unroll
    for (int e = 0; e < TE; e++) acc[e] = 0.f;
#pragma unroll 4
    for (int i = 0; i < TH/32; i++) {
        float xv = xr[i*32 + lane];
#pragma unroll
        for (int e = 0; e < TE; e++) acc[e] += xv * sgw[e*TH + i*32 + lane];
    }
#pragma unroll
    for (int off = 16; off; off >>= 1)
#pragma unroll
        for (int e = 0; e < TE; e++) acc[e] += __shfl_xor_sync(0xFFFFFFFFu, acc[e], off);
    if (lane == 0) {
        int best = 0; float bv = acc[0];
#pragma unroll
        for (int e = 1; e < TE; e++) if (acc[e] > bv) { bv = acc[e]; best = e; }
        g_expert_of[t] = best;
        atomicAdd(&g_count[best], 1);
    }
}

// ================= kernel 2: scan =================
__global__ void k_scan() {
    if (threadIdx.x == 0) {
        int s = 0;
        for (int e = 0; e < TE; e++) { g_offset[e] = s; s += g_count[e]; }
        g_offset[TE] = s;
    }
}

// ================= kernel 3: scatter =================
__global__ void k_scatter() {
    int t = blockIdx.x * blockDim.x + threadIdx.x;
    if (t < TT) {
        int e = g_expert_of[t];
        int p = g_offset[e] + atomicAdd(&g_cursor[e], 1);
        g_token_list[p] = t;
    }
}

// ================= kernel 4: up+gate HMMA GEMM (fp16 2-product) =========
// A = x split hi/lo fp16; B = weights single fp16. 2 MMAs per output tile.
#define SA_HI 0
#define SA_LO (128*RPAD)
#define SBG   (2*128*RPAD)
#define SBU   (2*128*RPAD + 64*RPAD)
#define G1_ELEMS (2*128*RPAD + 2*64*RPAD)
__global__ __launch_bounds__(256, 1) void k_upgate_mma(const float* __restrict__ x,
                                                       const float* __restrict__ wg,
                                                       const float* __restrict__ wu) {
    __shared__ __align__(16) __half sm[G1_ELEMS];
    __shared__ int rowsS[128];
    const int tid = threadIdx.x, wid = tid >> 5, lane = tid & 31;
    const int e = blockIdx.z;
    const int off = g_offset[e];
    const int cnt = g_offset[e+1] - off;
    const int m0 = blockIdx.x * 128;
    if (m0 >= cnt) return;
    const int n0 = blockIdx.y * 64;
    const int valid = (cnt - m0 < 128) ? (cnt - m0) : 128;

    if (tid < 128) {
        int m = m0 + tid;
        rowsS[tid] = (m < cnt) ? g_token_list[off + m] : -1;
    }
    __syncthreads();

    const float* wge = wg + (size_t)e * TH * TD;
    const float* wue = wu + (size_t)e * TH * TD;

    // A loader: thread -> (row, half): 16 consecutive k each
    const int arow = tid >> 1, ahalf = tid & 1;
    int tokA = rowsS[arow];
    if (tokA < 0) tokA = rowsS[0];
    const float* asrc = x + (size_t)tokA * TH + ahalf * 16;
    // B loader: thread -> (n, 8 k values)
    const int bn = tid & 63, bk8 = (tid >> 6) * 8;

    float cG[2][4][4], cU[2][4][4];
#pragma unroll
    for (int a = 0; a < 2; a++)
#pragma unroll
        for (int b = 0; b < 4; b++)
#pragma unroll
            for (int c = 0; c < 4; c++) { cG[a][b][c] = 0.f; cU[a][b][c] = 0.f; }

    const int wm = wid & 3, wn = wid >> 2;
    const uint32_t sb32 = smem_to_u32(sm);
    const int a_lr = ((lane >> 3) & 1) * 8 + (lane & 7);
    const int a_lk = (lane >> 4) * 8;
    const int b_lr = ((lane >> 4) & 1) * 8 + (lane & 7);
    const int b_lk = ((lane >> 3) & 1) * 8;
    const int qrow = lane >> 2, qcol = (lane & 3) * 2;

    // prefetch registers
    float4 pa[4];
    float  pg[8], pu[8];
#define G1_LOAD_REGS(c) do {                                              \
        int _k0 = (c) * 32;                                               \
        _Pragma("unroll")                                                 \
        for (int j = 0; j < 4; j++) pa[j] = *(const float4*)(asrc + _k0 + j*4); \
        _Pragma("unroll")                                                 \
        for (int j = 0; j < 8; j++) pg[j] = wge[(size_t)(_k0 + bk8 + j) * TD + n0 + bn]; \
        _Pragma("unroll")                                                 \
        for (int j = 0; j < 8; j++) pu[j] = wue[(size_t)(_k0 + bk8 + j) * TD + n0 + bn]; \
    } while (0)

    const int NC = TH / 32;   // 32
    G1_LOAD_REGS(0);
    for (int c = 0; c < NC; c++) {
        __syncthreads();   // previous compute done reading SMEM
        // ---- convert + store chunk c from registers ----
        {
            __align__(16) __half hb[16], lb[16];
#pragma unroll
            for (int j = 0; j < 4; j++) {
                split_f16(pa[j].x, hb[j*4+0], lb[j*4+0]);
                split_f16(pa[j].y, hb[j*4+1], lb[j*4+1]);
                split_f16(pa[j].z, hb[j*4+2], lb[j*4+2]);
                split_f16(pa[j].w, hb[j*4+3], lb[j*4+3]);
            }
            uint32_t ao = arow*RPAD + ahalf*16;
            *(uint4*)(sm + SA_HI + ao)     = ((uint4*)hb)[0];
            *(uint4*)(sm + SA_HI + ao + 8) = ((uint4*)hb)[1];
            *(uint4*)(sm + SA_LO + ao)     = ((uint4*)lb)[0];
            *(uint4*)(sm + SA_LO + ao + 8) = ((uint4*)lb)[1];
#pragma unroll
            for (int j = 0; j < 8; j++) hb[j] = __float2half_rn(pg[j]);
            *(uint4*)(sm + SBG + bn*RPAD + bk8) = *(uint4*)hb;
#pragma unroll
            for (int j = 0; j < 8; j++) hb[j] = __float2half_rn(pu[j]);
            *(uint4*)(sm + SBU + bn*RPAD + bk8) = *(uint4*)hb;
        }
        __syncthreads();   // stores visible
        if (c + 1 < NC) G1_LOAD_REGS(c + 1);   // overlap LDG with compute below
        // ---- compute chunk c (ldmatrix fragments, 2-product) ----
#pragma unroll
        for (int ks = 0; ks < 2; ks++) {
            uint32_t bG[8], bU[8];
#pragma unroll
            for (int p = 0; p < 2; p++) {
                uint32_t ro = (uint32_t)((wn*32 + p*16 + b_lr)*RPAD + ks*16 + b_lk) * 2;
                ldm_x4(bG[p*4+0], bG[p*4+1], bG[p*4+2], bG[p*4+3], sb32 + SBG*2 + ro);
                ldm_x4(bU[p*4+0], bU[p*4+1], bU[p*4+2], bU[p*4+3], sb32 + SBU*2 + ro);
            }
#pragma unroll
            for (int mt = 0; mt < 2; mt++) {
                uint32_t ao = (uint32_t)((wm*32 + mt*16 + a_lr)*RPAD + ks*16 + a_lk) * 2;
                uint32_t aH[4], aL[4];
                ldm_x4(aH[0], aH[1], aH[2], aH[3], sb32 + SA_HI*2 + ao);
                ldm_x4(aL[0], aL[1], aL[2], aL[3], sb32 + SA_LO*2 + ao);
#pragma unroll
                for (int nt = 0; nt < 4; nt++) {
                    mma_f16(cG[mt][nt], aH, &bG[nt*2]);
                    mma_f16(cG[mt][nt], aL, &bG[nt*2]);
                    mma_f16(cU[mt][nt], aH, &bU[nt*2]);
                    mma_f16(cU[mt][nt], aL, &bU[nt*2]);
                }
            }
        }
    }

    // epilogue: inter = relu(g)^2 * u, fp32 store to permuted rows
#pragma unroll
    for (int mt = 0; mt < 2; mt++)
#pragma unroll
        for (int h = 0; h < 2; h++) {
            int rr = wm*32 + mt*16 + qrow + h*8;
            if (rr < valid) {
                float* rowp = g_inter + (size_t)(off + m0 + rr) * TD + n0;
#pragma unroll
                for (int nt = 0; nt < 4; nt++) {
                    float g0 = fmaxf(cG[mt][nt][h*2+0], 0.f);
                    float g1 = fmaxf(cG[mt][nt][h*2+1], 0.f);
                    float2 v = make_float2(g0*g0*cU[mt][nt][h*2+0],
                                           g1*g1*cU[mt][nt][h*2+1]);
                    *(float2*)(rowp + wn*32 + nt*8 + qcol) = v;
                }
            }
        }
}

// ================= kernel 5: down-proj HMMA GEMM (fp16 2-product) + scatter =========
#define D_SA_HI 0
#define D_SA_LO (128*RPAD)
#define D_SB    (2*128*RPAD)
#define G2_ELEMS (2*128*RPAD + 64*RPAD)
__global__ __launch_bounds__(256, 1) void k_down_mma(const float* __restrict__ wd,
                                                     float* __restrict__ out) {
    __shared__ __align__(16) __half sm[G2_ELEMS];
    __shared__ int rowsS[128];
    const int tid = threadIdx.x, wid = tid >> 5, lane = tid & 31;
    const int e = blockIdx.z;
    const int off = g_offset[e];
    const int cnt = g_offset[e+1] - off;
    const int m0 = blockIdx.x * 128;
    if (m0 >= cnt) return;
    const int n0 = blockIdx.y * 64;
    const int valid = (cnt - m0 < 128) ? (cnt - m0) : 128;

    if (tid < 128) {
        int m = m0 + tid;
        rowsS[tid] = (m < cnt) ? g_token_list[off + m] : -1;
    }
    __syncthreads();

    const float* wde = wd + (size_t)e * TD * TH;

    const int arow = tid >> 1, ahalf = tid & 1;
    const int arowc = (arow < valid) ? arow : (valid - 1);
    const float* asrc = g_inter + (size_t)(off + m0 + arowc) * TD + ahalf * 16;
    const int bn = tid & 63, bk8 = (tid >> 6) * 8;

    float cc[2][4][4];
#pragma unroll
    for (int a = 0; a < 2; a++)
#pragma unroll
        for (int b = 0; b < 4; b++)
#pragma unroll
            for (int c = 0; c < 4; c++) cc[a][b][c] = 0.f;

    const int wm = wid & 3, wn = wid >> 2;
    const uint32_t sb32 = smem_to_u32(sm);
    const int a_lr = ((lane >> 3) & 1) * 8 + (lane & 7);
    const int a_lk = (lane >> 4) * 8;
    const int b_lr = ((lane >> 4) & 1) * 8 + (lane & 7);
    const int b_lk = ((lane >> 3) & 1) * 8;
    const int qrow = lane >> 2, qcol = (lane & 3) * 2;

    float4 pa[4];
    float  pb[8];
#define G2_LOAD_REGS(c) do {                                              \
        int _k0 = (c) * 32;                                               \
        _Pragma("unroll")                                                 \
        for (int j = 0; j < 4; j++) pa[j] = *(const float4*)(asrc + _k0 + j*4); \
        _Pragma("unroll")                                                 \
        for (int j = 0; j < 8; j++) pb[j] = wde[(size_t)(_k0 + bk8 + j) * TH + n0 + bn]; \
    } while (0)

    const int NC = TD / 32;   // 8
    G2_LOAD_REGS(0);
    for (int c = 0; c < NC; c++) {
        __syncthreads();
        {
            __align__(16) __half hb[16], lb[16];
#pragma unroll
            for (int j = 0; j < 4; j++) {
                split_f16(pa[j].x, hb[j*4+0], lb[j*4+0]);
                split_f16(pa[j].y, hb[j*4+1], lb[j*4+1]);
                split_f16(pa[j].z, hb[j*4+2], lb[j*4+2]);
                split_f16(pa[j].w, hb[j*4+3], lb[j*4+3]);
            }
            uint32_t ao = arow*RPAD + ahalf*16;
            *(uint4*)(sm + D_SA_HI + ao)     = ((uint4*)hb)[0];
            *(uint4*)(sm + D_SA_HI + ao + 8) = ((uint4*)hb)[1];
            *(uint4*)(sm + D_SA_LO + ao)     = ((uint4*)lb)[0];
            *(uint4*)(sm + D_SA_LO + ao + 8) = ((uint4*)lb)[1];
#pragma unroll
            for (int j = 0; j < 8; j++) hb[j] = __float2half_rn(pb[j]);
            *(uint4*)(sm + D_SB + bn*RPAD + bk8) = *(uint4*)hb;
        }
        __syncthreads();
        if (c + 1 < NC) G2_LOAD_REGS(c + 1);
#pragma unroll
        for (int ks = 0; ks < 2; ks++) {
            uint32_t bB[8];
#pragma unroll
            for (int p = 0; p < 2; p++) {
                uint32_t ro = (uint32_t)((wn*32 + p*16 + b_lr)*RPAD + ks*16 + b_lk) * 2;
                ldm_x4(bB[p*4+0], bB[p*4+1], bB[p*4+2], bB[p*4+3], sb32 + D_SB*2 + ro);
            }
#pragma unroll
            for (int mt = 0; mt < 2; mt++) {
                uint32_t ao = (uint32_t)((wm*32 + mt*16 + a_lr)*RPAD + ks*16 + a_lk) * 2;
                uint32_t aH[4], aL[4];
                ldm_x4(aH[0], aH[1], aH[2], aH[3], sb32 + D_SA_HI*2 + ao);
                ldm_x4(aL[0], aL[1], aL[2], aL[3], sb32 + D_SA_LO*2 + ao);
#pragma unroll
                for (int nt = 0; nt < 4; nt++) {
                    mma_f16(cc[mt][nt], aH, &bB[nt*2]);
                    mma_f16(cc[mt][nt], aL, &bB[nt*2]);
                }
            }
        }
    }

    // epilogue: scatter-store fp32 pairs to out[token]
#pragma unroll
    for (int mt = 0; mt < 2; mt++)
#pragma unroll
        for (int h = 0; h < 2; h++) {
            int rr = wm*32 + mt*16 + qrow + h*8;
            int tok = rowsS[rr];
            if (tok >= 0) {
                float* rowp = out + (size_t)tok * TH + n0;
#pragma unroll
                for (int nt = 0; nt < 4; nt++) {
                    float2 v = make_float2(cc[mt][nt][h*2+0], cc[mt][nt][h*2+1]);
                    *(float2*)(rowp + wn*32 + nt*8 + qcol) = v;
                }
            }
        }
}

// ================= launch =================
extern "C" void kernel_launch(void* const* d_in, const int* in_sizes, int n_in,
                              void* d_out, int out_size) {
    const float* x  = (const float*)d_in[0];   // [B,S,H]
    const float* gw = (const float*)d_in[1];   // [E,H]
    const float* wg = (const float*)d_in[2];   // [E,H,D]
    const float* wu = (const float*)d_in[3];   // [E,H,D]
    const float* wd = (const float*)d_in[4];   // [E,D,H]
    float* out = (float*)d_out;

    k_zero<<<1, 32>>>();
    k_router<<<TT/8, 256>>>(x, gw);
    k_scan<<<1, 32>>>();
    k_scatter<<<TT/256, 256>>>();
    {
        dim3 grid(TT/128, TD/64, TE);   // (128, 4, 8); idle tiles exit on count check
        k_upgate_mma<<<grid, 256>>>(x, wg, wu);
    }
    {
        dim3 grid(TT/128, TH/64, TE);   // (128, 16, 8)
        k_down_mma<<<grid, 256>>>(wd, out);
    }
}